// round 3
// baseline (speedup 1.0000x reference)
#include <cuda_runtime.h>

// RNN: B=4096, T=512, I=1, H=16, O=1
//   a_t[j] = x_t*w_ih[j] + b_ih[j] + b_hh[j] + sum_k w_hh[j][k]*h_{t-1}[k]
//   h_t = tanh(a_t),  h_0 = 0;  out[b] = dot(h_T, w_fc) + b_fc
//
// Mapping: 16 lanes per batch element (lane j owns unit j); 2 batch elems
// per warp -> 2048 warps. Recurrence carried in r-space:
//   r = 1/(1 + 2^(K*a)),  K = 2*log2(e),  h = 1 - 2r  (h0=0 -> r0=0.5)
// with (1-2r) and K folded into per-lane constants.
// Per step: 16 front-loaded SHFLs of r, 17-FMA tree (4 accumulators),
// EX2 + FADD + RCP.
// R3: x software-pipelined with prefetch distance 2 (hides ~577cyc DRAM
// latency under ~8 steps of compute); 64-thread blocks for SM balance.

#define RNN_B 4096
#define RNN_T 512
#define RNN_H 16

__device__ __forceinline__ float ex2_approx(float x) {
    float y;
    asm("ex2.approx.f32 %0, %1;" : "=f"(y) : "f"(x));
    return y;
}
__device__ __forceinline__ float rcp_approx(float x) {
    float y;
    asm("rcp.approx.f32 %0, %1;" : "=f"(y) : "f"(x));
    return y;
}

__global__ __launch_bounds__(64) void rnn_scan_kernel(
    const float* __restrict__ x,      // [B, T, 1]
    const float* __restrict__ w_ih,   // [H, 1]
    const float* __restrict__ w_hh,   // [H, H]
    const float* __restrict__ b_ih,   // [H]
    const float* __restrict__ b_hh,   // [H]
    const float* __restrict__ w_fc,   // [1, H]
    const float* __restrict__ b_fc,   // [1]
    float* __restrict__ out)          // [B, 1]
{
    const int tid  = blockIdx.x * blockDim.x + threadIdx.x;
    const int warp = tid >> 5;
    const int lane = tid & 31;
    const int sub  = lane >> 4;   // batch element within warp (0/1)
    const int j    = lane & 15;   // hidden unit owned by this lane

    const int b = warp * 2 + sub; // always < 4096

    const float K = 2.8853900817779268f; // 2*log2(e)

    // Per-lane folded constants.
    float wfold[RNN_H];
    float wsum = 0.0f;
    {
        const float4* w4 = reinterpret_cast<const float4*>(w_hh + j * RNN_H);
        float4 a0 = w4[0], a1 = w4[1], a2 = w4[2], a3 = w4[3];
        float wr[RNN_H] = {a0.x,a0.y,a0.z,a0.w, a1.x,a1.y,a1.z,a1.w,
                           a2.x,a2.y,a2.z,a2.w, a3.x,a3.y,a3.z,a3.w};
        #pragma unroll
        for (int k = 0; k < RNN_H; k++) {
            wsum += wr[k];
            wfold[k] = -2.0f * K * wr[k];
        }
    }
    const float wihK  = K * w_ih[j];
    const float biasK = K * (b_ih[j] + b_hh[j] + wsum);

    const float4* x4 = reinterpret_cast<const float4*>(x + (long)b * RNN_T);

    float r = 0.5f;  // h0 = 0  <=>  r0 = 0.5

    // Software pipeline on x: prefetch distance 2 (8 steps of compute in
    // flight behind each load -> DRAM latency fully hidden).
    float4 cur = x4[0];
    float4 nxt = x4[1];

    #pragma unroll 1
    for (int t4 = 0; t4 < RNN_T / 4; t4++) {
        const int pfi = t4 + 2 < RNN_T / 4 ? t4 + 2 : RNN_T / 4 - 1;
        const float4 pf = x4[pfi];

        float xs[4] = {cur.x, cur.y, cur.z, cur.w};
        #pragma unroll
        for (int s = 0; s < 4; s++) {
            // Front-load all 16 independent shuffles of r.
            float rv[RNN_H];
            #pragma unroll
            for (int k = 0; k < RNN_H; k++)
                rv[k] = __shfl_sync(0xffffffffu, r, k, 16);

            // 4-way accumulation tree.
            float a0 = fmaf(xs[s], wihK, biasK);
            float a1 = wfold[1] * rv[1];
            float a2 = wfold[2] * rv[2];
            float a3 = wfold[3] * rv[3];
            a0 = fmaf(wfold[0], rv[0], a0);
            #pragma unroll
            for (int k = 4; k < RNN_H; k += 4) {
                a0 = fmaf(wfold[k + 0], rv[k + 0], a0);
                a1 = fmaf(wfold[k + 1], rv[k + 1], a1);
                a2 = fmaf(wfold[k + 2], rv[k + 2], a2);
                a3 = fmaf(wfold[k + 3], rv[k + 3], a3);
            }
            float acc = (a0 + a1) + (a2 + a3);

            // r = 1/(1 + 2^acc)
            r = rcp_approx(1.0f + ex2_approx(acc));
        }

        cur = nxt;
        nxt = pf;
    }

    // h_T = 1 - 2r; out[b] = sum_j h_j * w_fc[j] + b_fc
    float h = fmaf(-2.0f, r, 1.0f);
    float v = h * w_fc[j];
    #pragma unroll
    for (int off = 8; off; off >>= 1)
        v += __shfl_xor_sync(0xffffffffu, v, off, 16);
    if (j == 0)
        out[b] = v + b_fc[0];
}

extern "C" void kernel_launch(void* const* d_in, const int* in_sizes, int n_in,
                              void* d_out, int out_size) {
    const float* x    = (const float*)d_in[0];
    const float* w_ih = (const float*)d_in[1];
    const float* w_hh = (const float*)d_in[2];
    const float* b_ih = (const float*)d_in[3];
    const float* b_hh = (const float*)d_in[4];
    const float* w_fc = (const float*)d_in[5];
    const float* b_fc = (const float*)d_in[6];
    float* out = (float*)d_out;

    // 64-thread blocks -> 1024 blocks -> near-perfect SM balance (max 14
    // warps/SM vs 13.84 average), vs 16/13.84 with 128-thread blocks.
    const int threads = 64;
    const int blocks  = (RNN_B * RNN_H) / threads; // 1024 blocks, 2048 warps
    rnn_scan_kernel<<<blocks, threads>>>(x, w_ih, w_hh, b_ih, b_hh, w_fc, b_fc, out);
}

// round 4
// speedup vs baseline: 1.4061x; 1.4061x over previous
#include <cuda_runtime.h>

// RNN: B=4096, T=512, I=1, H=16, O=1
//   a_t[j] = x_t*w_ih[j] + b_ih[j] + b_hh[j] + sum_k w_hh[j][k]*h_{t-1}[k]
//   h_t = tanh(a_t),  h_0 = 0;  out[b] = dot(h_T, w_fc) + b_fc
//
// R4 mapping: 8 lanes per batch element, each lane owns 2 hidden units
// (j0 = m, j1 = m + 8, m = lane&7); 4 batch elements per warp -> 1024 warps.
// Rationale: R2/R3 ncu showed the SM-wide shuffle unit at ~63% (the "L1"
// pipe) as the binder; halving SHFLs per element-step (16 width-8 SHFLs now
// serve 4 elements) trades shuffle pressure for FMA pressure, which has 8x
// the headroom.
//
// Recurrence carried in r-space: r = 1/(1 + 2^(K*a)), K = 2*log2(e),
// h = 1 - 2r (h0=0 -> r0=0.5), with (1-2r) and K folded into constants:
//   acc_j = biasK[j] + x*wihK[j] + sum_k wfold[j][k]*r[k]

#define RNN_B 4096
#define RNN_T 512
#define RNN_H 16

__device__ __forceinline__ float ex2_approx(float x) {
    float y;
    asm("ex2.approx.f32 %0, %1;" : "=f"(y) : "f"(x));
    return y;
}
__device__ __forceinline__ float rcp_approx(float x) {
    float y;
    asm("rcp.approx.f32 %0, %1;" : "=f"(y) : "f"(x));
    return y;
}

__global__ __launch_bounds__(32) void rnn_scan_kernel(
    const float* __restrict__ x,      // [B, T, 1]
    const float* __restrict__ w_ih,   // [H, 1]
    const float* __restrict__ w_hh,   // [H, H]
    const float* __restrict__ b_ih,   // [H]
    const float* __restrict__ b_hh,   // [H]
    const float* __restrict__ w_fc,   // [1, H]
    const float* __restrict__ b_fc,   // [1]
    float* __restrict__ out)          // [B, 1]
{
    const int tid  = blockIdx.x * blockDim.x + threadIdx.x;
    const int warp = tid >> 5;
    const int lane = tid & 31;
    const int g    = lane >> 3;   // batch element within warp (0..3)
    const int m    = lane & 7;    // lane within 8-lane group

    const int b  = warp * 4 + g;  // always < 4096
    const int j0 = m;             // first hidden unit owned by this lane
    const int j1 = m + 8;         // second hidden unit

    const float K = 2.8853900817779268f; // 2*log2(e)

    // Per-lane folded constants for both owned rows.
    float wf0[RNN_H], wf1[RNN_H];
    float wsum0 = 0.0f, wsum1 = 0.0f;
    {
        const float4* wa = reinterpret_cast<const float4*>(w_hh + j0 * RNN_H);
        const float4* wb = reinterpret_cast<const float4*>(w_hh + j1 * RNN_H);
        #pragma unroll
        for (int q = 0; q < 4; q++) {
            float4 ra = wa[q], rb = wb[q];
            float va[4] = {ra.x, ra.y, ra.z, ra.w};
            float vb[4] = {rb.x, rb.y, rb.z, rb.w};
            #pragma unroll
            for (int e = 0; e < 4; e++) {
                wsum0 += va[e];
                wsum1 += vb[e];
                wf0[q * 4 + e] = -2.0f * K * va[e];
                wf1[q * 4 + e] = -2.0f * K * vb[e];
            }
        }
    }
    const float wihK0  = K * w_ih[j0];
    const float wihK1  = K * w_ih[j1];
    const float biasK0 = K * (b_ih[j0] + b_hh[j0] + wsum0);
    const float biasK1 = K * (b_ih[j1] + b_hh[j1] + wsum1);

    const float4* x4 = reinterpret_cast<const float4*>(x + (long)b * RNN_T);

    float r0 = 0.5f, r1 = 0.5f;  // h0 = 0  <=>  r = 0.5

    #pragma unroll 1
    for (int t4 = 0; t4 < RNN_T / 4; t4++) {
        const float4 xv = x4[t4];
        float xs[4] = {xv.x, xv.y, xv.z, xv.w};
        #pragma unroll
        for (int s = 0; s < 4; s++) {
            // Gather all 16 r values: h[k]=r0 of lane k (k<8), h[k+8]=r1.
            float rv[RNN_H];
            #pragma unroll
            for (int k = 0; k < 8; k++)
                rv[k] = __shfl_sync(0xffffffffu, r0, k, 8);
            #pragma unroll
            for (int k = 0; k < 8; k++)
                rv[k + 8] = __shfl_sync(0xffffffffu, r1, k, 8);

            // Row j0: 4-way accumulation tree.
            float a0 = fmaf(xs[s], wihK0, biasK0);
            float a1 = wf0[1] * rv[1];
            float a2 = wf0[2] * rv[2];
            float a3 = wf0[3] * rv[3];
            a0 = fmaf(wf0[0], rv[0], a0);
            // Row j1: 4-way accumulation tree (independent, interleaves).
            float c0 = fmaf(xs[s], wihK1, biasK1);
            float c1 = wf1[1] * rv[1];
            float c2 = wf1[2] * rv[2];
            float c3 = wf1[3] * rv[3];
            c0 = fmaf(wf1[0], rv[0], c0);
            #pragma unroll
            for (int k = 4; k < RNN_H; k += 4) {
                a0 = fmaf(wf0[k + 0], rv[k + 0], a0);
                a1 = fmaf(wf0[k + 1], rv[k + 1], a1);
                a2 = fmaf(wf0[k + 2], rv[k + 2], a2);
                a3 = fmaf(wf0[k + 3], rv[k + 3], a3);
                c0 = fmaf(wf1[k + 0], rv[k + 0], c0);
                c1 = fmaf(wf1[k + 1], rv[k + 1], c1);
                c2 = fmaf(wf1[k + 2], rv[k + 2], c2);
                c3 = fmaf(wf1[k + 3], rv[k + 3], c3);
            }
            float accA = (a0 + a1) + (a2 + a3);
            float accC = (c0 + c1) + (c2 + c3);

            // r = 1/(1 + 2^acc)
            r0 = rcp_approx(1.0f + ex2_approx(accA));
            r1 = rcp_approx(1.0f + ex2_approx(accC));
        }
    }

    // h = 1 - 2r; out[b] = sum_j h[j]*w_fc[j] + b_fc
    float h0 = fmaf(-2.0f, r0, 1.0f);
    float h1 = fmaf(-2.0f, r1, 1.0f);
    float v = h0 * w_fc[j0] + h1 * w_fc[j1];
    #pragma unroll
    for (int off = 4; off; off >>= 1)
        v += __shfl_xor_sync(0xffffffffu, v, off, 8);
    if (m == 0)
        out[b] = v + b_fc[0];
}

extern "C" void kernel_launch(void* const* d_in, const int* in_sizes, int n_in,
                              void* d_out, int out_size) {
    const float* x    = (const float*)d_in[0];
    const float* w_ih = (const float*)d_in[1];
    const float* w_hh = (const float*)d_in[2];
    const float* b_ih = (const float*)d_in[3];
    const float* b_hh = (const float*)d_in[4];
    const float* w_fc = (const float*)d_in[5];
    const float* b_fc = (const float*)d_in[6];
    float* out = (float*)d_out;

    // 4096 elems * 8 lanes = 32768 threads = 1024 warps; 32-thread blocks
    // spread as 7 warps/SM max (vs 8 with larger blocks).
    const int threads = 32;
    const int blocks  = (RNN_B * 8) / threads; // 1024
    rnn_scan_kernel<<<blocks, threads>>>(x, w_ih, w_hh, b_ih, b_hh, w_fc, b_fc, out);
}

// round 5
// speedup vs baseline: 1.5208x; 1.0816x over previous
#include <cuda_runtime.h>

// RNN: B=4096, T=512, I=1, H=16, O=1
//   a_t[j] = x_t*w_ih[j] + b_ih[j] + b_hh[j] + sum_k w_hh[j][k]*h_{t-1}[k]
//   h_t = tanh(a_t),  h_0 = 0;  out[b] = dot(h_T, w_fc) + b_fc
//
// R4 mapping (kept): 8 lanes per batch element, 2 hidden units per lane
// (j0=m, j1=m+8), 4 batch elements per warp -> 1024 warps.
// R5: x staged through shared memory. Each warp's 4 sequences are 8KB
// contiguous in x; preloaded once with 16 coalesced LDG.128 (latency paid
// once, high MLP), then the recurrence reads x via broadcast LDS.128 —
// removing the ~577-cycle DRAM latency that R4 ate every 4 steps (the gap
// between the ~130cyc/step compute chain and the measured ~296cyc/step).
//
// Recurrence in r-space: r = 1/(1 + 2^(K*a)), K = 2*log2(e), h = 1-2r
// (h0=0 -> r0=0.5), with (1-2r) and K folded into per-lane constants.

#define RNN_B 4096
#define RNN_T 512
#define RNN_H 16

// Row stride in floats for the smem x tile: 512 + 4 pad so the 4 groups'
// LDS.128 reads hit different banks (2064B row stride -> 4-bank shift).
#define XROW (RNN_T + 4)

__device__ __forceinline__ float ex2_approx(float x) {
    float y;
    asm("ex2.approx.f32 %0, %1;" : "=f"(y) : "f"(x));
    return y;
}
__device__ __forceinline__ float rcp_approx(float x) {
    float y;
    asm("rcp.approx.f32 %0, %1;" : "=f"(y) : "f"(x));
    return y;
}

__global__ __launch_bounds__(32) void rnn_scan_kernel(
    const float* __restrict__ x,      // [B, T, 1]
    const float* __restrict__ w_ih,   // [H, 1]
    const float* __restrict__ w_hh,   // [H, H]
    const float* __restrict__ b_ih,   // [H]
    const float* __restrict__ b_hh,   // [H]
    const float* __restrict__ w_fc,   // [1, H]
    const float* __restrict__ b_fc,   // [1]
    float* __restrict__ out)          // [B, 1]
{
    __shared__ float sx[4 * XROW];    // 4 sequences, padded rows (~8.3KB)

    const int warp = blockIdx.x;      // 1 warp per block
    const int lane = threadIdx.x;     // 0..31
    const int g    = lane >> 3;       // batch element within warp (0..3)
    const int m    = lane & 7;        // lane within 8-lane group

    const int b  = warp * 4 + g;      // always < 4096
    const int j0 = m;
    const int j1 = m + 8;

    // ---- Preload this warp's 4 contiguous sequences (8KB) into smem. ----
    {
        const float4* src = reinterpret_cast<const float4*>(x + (long)warp * 4 * RNN_T);
        #pragma unroll
        for (int i = 0; i < 16; i++) {
            const int idx = i * 32 + lane;        // float4 index, 0..511
            const float4 v = src[idx];
            const int f  = idx * 4;               // float index in 4*512
            const int row = f >> 9;               // /512
            const int col = f & 511;
            *reinterpret_cast<float4*>(&sx[row * XROW + col]) = v;
        }
    }

    const float K = 2.8853900817779268f; // 2*log2(e)

    // Per-lane folded constants for both owned rows.
    float wf0[RNN_H], wf1[RNN_H];
    float wsum0 = 0.0f, wsum1 = 0.0f;
    {
        const float4* wa = reinterpret_cast<const float4*>(w_hh + j0 * RNN_H);
        const float4* wb = reinterpret_cast<const float4*>(w_hh + j1 * RNN_H);
        #pragma unroll
        for (int q = 0; q < 4; q++) {
            float4 ra = wa[q], rb = wb[q];
            float va[4] = {ra.x, ra.y, ra.z, ra.w};
            float vb[4] = {rb.x, rb.y, rb.z, rb.w};
            #pragma unroll
            for (int e = 0; e < 4; e++) {
                wsum0 += va[e];
                wsum1 += vb[e];
                wf0[q * 4 + e] = -2.0f * K * va[e];
                wf1[q * 4 + e] = -2.0f * K * vb[e];
            }
        }
    }
    const float wihK0  = K * w_ih[j0];
    const float wihK1  = K * w_ih[j1];
    const float biasK0 = K * (b_ih[j0] + b_hh[j0] + wsum0);
    const float biasK1 = K * (b_ih[j1] + b_hh[j1] + wsum1);

    __syncthreads();  // smem x tile ready (single-warp block)

    const float4* sx4 = reinterpret_cast<const float4*>(&sx[g * XROW]);

    float r0 = 0.5f, r1 = 0.5f;  // h0 = 0  <=>  r = 0.5

    #pragma unroll 1
    for (int t4 = 0; t4 < RNN_T / 4; t4++) {
        const float4 xv = sx4[t4];   // broadcast LDS.128 within each group
        float xs[4] = {xv.x, xv.y, xv.z, xv.w};
        #pragma unroll
        for (int s = 0; s < 4; s++) {
            // Gather all 16 r values: h[k]=r0 of lane k (k<8), h[k+8]=r1.
            float rv[RNN_H];
            #pragma unroll
            for (int k = 0; k < 8; k++)
                rv[k] = __shfl_sync(0xffffffffu, r0, k, 8);
            #pragma unroll
            for (int k = 0; k < 8; k++)
                rv[k + 8] = __shfl_sync(0xffffffffu, r1, k, 8);

            // Two interleaved 4-way accumulation trees.
            float a0 = fmaf(xs[s], wihK0, biasK0);
            float a1 = wf0[1] * rv[1];
            float a2 = wf0[2] * rv[2];
            float a3 = wf0[3] * rv[3];
            a0 = fmaf(wf0[0], rv[0], a0);
            float c0 = fmaf(xs[s], wihK1, biasK1);
            float c1 = wf1[1] * rv[1];
            float c2 = wf1[2] * rv[2];
            float c3 = wf1[3] * rv[3];
            c0 = fmaf(wf1[0], rv[0], c0);
            #pragma unroll
            for (int k = 4; k < RNN_H; k += 4) {
                a0 = fmaf(wf0[k + 0], rv[k + 0], a0);
                a1 = fmaf(wf0[k + 1], rv[k + 1], a1);
                a2 = fmaf(wf0[k + 2], rv[k + 2], a2);
                a3 = fmaf(wf0[k + 3], rv[k + 3], a3);
                c0 = fmaf(wf1[k + 0], rv[k + 0], c0);
                c1 = fmaf(wf1[k + 1], rv[k + 1], c1);
                c2 = fmaf(wf1[k + 2], rv[k + 2], c2);
                c3 = fmaf(wf1[k + 3], rv[k + 3], c3);
            }
            float accA = (a0 + a1) + (a2 + a3);
            float accC = (c0 + c1) + (c2 + c3);

            // r = 1/(1 + 2^acc)
            r0 = rcp_approx(1.0f + ex2_approx(accA));
            r1 = rcp_approx(1.0f + ex2_approx(accC));
        }
    }

    // h = 1 - 2r; out[b] = sum_j h[j]*w_fc[j] + b_fc
    float h0 = fmaf(-2.0f, r0, 1.0f);
    float h1 = fmaf(-2.0f, r1, 1.0f);
    float v = h0 * w_fc[j0] + h1 * w_fc[j1];
    #pragma unroll
    for (int off = 4; off; off >>= 1)
        v += __shfl_xor_sync(0xffffffffu, v, off, 8);
    if (m == 0)
        out[b] = v + b_fc[0];
}

extern "C" void kernel_launch(void* const* d_in, const int* in_sizes, int n_in,
                              void* d_out, int out_size) {
    const float* x    = (const float*)d_in[0];
    const float* w_ih = (const float*)d_in[1];
    const float* w_hh = (const float*)d_in[2];
    const float* b_ih = (const float*)d_in[3];
    const float* b_hh = (const float*)d_in[4];
    const float* w_fc = (const float*)d_in[5];
    const float* b_fc = (const float*)d_in[6];
    float* out = (float*)d_out;

    // 1024 single-warp blocks; 4 batch elements per warp.
    rnn_scan_kernel<<<RNN_B / 4, 32>>>(x, w_ih, w_hh, b_ih, b_hh, w_fc, b_fc, out);
}

// round 6
// speedup vs baseline: 1.6284x; 1.0708x over previous
#include <cuda_runtime.h>

// RNN: B=4096, T=512, I=1, H=16, O=1
//   h_t = tanh(x_t*w_ih + b_ih + b_hh + W_hh h_{t-1}), h_0=0
//   out[b] = dot(h_T, w_fc) + b_fc
//
// R6 mapping: 16 lanes per batch element, lane j owns row j; 2 elements per
// warp -> 2048 warps, 1 warp per block.
//  - Recurrence in r-space: r = 1/(1+2^(K*a)), K=2*log2(e), h=1-2r (r0=0.5),
//    with (1-2r) and K folded into per-lane packed weights.
//  - h broadcast via double-buffered smem: STS.32 + syncwarp + 4x
//    ld.shared.v2.u64 -> 8 f32x2 pairs, ready-packed (replaces 16 SHFLs).
//  - Dot product with packed fma.rn.f32x2 (2 mul2 + 6 fma2, two chains) —
//    halves fma-pipe issue vs 16 scalar FFMA.
//  - x staged in smem once per warp (R5), LDS.128 per 4 steps.

#define RNN_B 4096
#define RNN_T 512
#define RNN_H 16
#define XROW (RNN_T + 4)   // pad: groups' x reads land on different banks
#define HROW 20            // h row stride (floats): 16B-aligned, bank-staggered

__device__ __forceinline__ float ex2_approx(float x) {
    float y; asm("ex2.approx.f32 %0, %1;" : "=f"(y) : "f"(x)); return y;
}
__device__ __forceinline__ float rcp_approx(float x) {
    float y; asm("rcp.approx.f32 %0, %1;" : "=f"(y) : "f"(x)); return y;
}
__device__ __forceinline__ unsigned long long mul2(unsigned long long a, unsigned long long b) {
    unsigned long long d; asm("mul.rn.f32x2 %0, %1, %2;" : "=l"(d) : "l"(a), "l"(b)); return d;
}
__device__ __forceinline__ unsigned long long fma2(unsigned long long a, unsigned long long b, unsigned long long c) {
    unsigned long long d; asm("fma.rn.f32x2 %0, %1, %2, %3;" : "=l"(d) : "l"(a), "l"(b), "l"(c)); return d;
}
__device__ __forceinline__ unsigned long long add2(unsigned long long a, unsigned long long b) {
    unsigned long long d; asm("add.rn.f32x2 %0, %1, %2;" : "=l"(d) : "l"(a), "l"(b)); return d;
}
__device__ __forceinline__ unsigned long long packf2(float lo, float hi) {
    unsigned long long d; asm("mov.b64 %0, {%1, %2};" : "=l"(d) : "f"(lo), "f"(hi)); return d;
}
__device__ __forceinline__ float2 unpackf2(unsigned long long p) {
    float lo, hi; asm("mov.b64 {%0, %1}, %2;" : "=f"(lo), "=f"(hi) : "l"(p));
    return make_float2(lo, hi);
}
__device__ __forceinline__ void lds_v2u64(unsigned saddr, unsigned long long& a, unsigned long long& b) {
    asm volatile("ld.shared.v2.u64 {%0, %1}, [%2];" : "=l"(a), "=l"(b) : "r"(saddr));
}
__device__ __forceinline__ void sts_f32(unsigned saddr, float v) {
    asm volatile("st.shared.f32 [%0], %1;" :: "r"(saddr), "f"(v));
}

__global__ __launch_bounds__(32) void rnn_scan_kernel(
    const float* __restrict__ x,      // [B, T, 1]
    const float* __restrict__ w_ih,   // [H]
    const float* __restrict__ w_hh,   // [H, H]
    const float* __restrict__ b_ih,   // [H]
    const float* __restrict__ b_hh,   // [H]
    const float* __restrict__ w_fc,   // [H]
    const float* __restrict__ b_fc,   // [1]
    float* __restrict__ out)          // [B]
{
    __shared__ __align__(16) float sx[2 * XROW];      // 2 sequences of x
    __shared__ __align__(16) float hb[2][2 * HROW];   // double-buffered r

    const int warp = blockIdx.x;      // one warp per block
    const int lane = threadIdx.x;     // 0..31
    const int sub  = lane >> 4;       // batch element within warp (0/1)
    const int j    = lane & 15;       // hidden row owned by this lane

    const int b = warp * 2 + sub;     // < 4096

    // ---- Preload this warp's 2 contiguous x sequences (4KB) into smem. ----
    {
        const float4* src = reinterpret_cast<const float4*>(x + (long)warp * 2 * RNN_T);
        #pragma unroll
        for (int i = 0; i < 8; i++) {
            const int idx = i * 32 + lane;        // float4 index 0..255
            const float4 v = src[idx];
            const int f   = idx * 4;
            const int row = f >> 9;               // /512
            const int col = f & 511;
            *reinterpret_cast<float4*>(&sx[row * XROW + col]) = v;
        }
    }

    const float K = 2.8853900817779268f; // 2*log2(e)

    // Packed folded weights: wp[k] = (-2K*w[j][2k], -2K*w[j][2k+1])
    unsigned long long wp[8];
    float wsum = 0.0f;
    {
        const float4* w4 = reinterpret_cast<const float4*>(w_hh + j * RNN_H);
        #pragma unroll
        for (int q = 0; q < 4; q++) {
            float4 rw = w4[q];
            float v0 = rw.x, v1 = rw.y, v2 = rw.z, v3 = rw.w;
            wsum += (v0 + v1) + (v2 + v3);
            wp[q * 2 + 0] = packf2(-2.0f * K * v0, -2.0f * K * v1);
            wp[q * 2 + 1] = packf2(-2.0f * K * v2, -2.0f * K * v3);
        }
    }
    const float wihK  = K * w_ih[j];
    const float biasK = K * (b_ih[j] + b_hh[j] + wsum);

    // Shared addresses (32-bit, shared window).
    const unsigned rA = (unsigned)__cvta_generic_to_shared(&hb[0][sub * HROW]);
    const unsigned rB = (unsigned)__cvta_generic_to_shared(&hb[1][sub * HROW]);
    const unsigned wA = rA + 4u * j;  // this lane's slot in buffer A
    const unsigned wB = rB + 4u * j;  // and in buffer B

    // Init: r0 = 0.5 (h0 = 0) into buffer A.
    sts_f32(wA, 0.5f);
    __syncwarp();

    const float4* sx4 = reinterpret_cast<const float4*>(&sx[sub * XROW]);

    float r = 0.5f;

    #pragma unroll 1
    for (int t4 = 0; t4 < RNN_T / 4; t4++) {
        const float4 xv = sx4[t4];    // broadcast LDS.128 within each group
        const float xs[4] = {xv.x, xv.y, xv.z, xv.w};
        #pragma unroll
        for (int s = 0; s < 4; s++) {
            // s even: read A, write B;  s odd: read B, write A.
            const unsigned rbase = (s & 1) ? rB : rA;
            const unsigned waddr = (s & 1) ? wA : wB;

            // Gather 16 r values as 8 ready-packed f32x2 pairs.
            unsigned long long rp[8];
            lds_v2u64(rbase +  0, rp[0], rp[1]);
            lds_v2u64(rbase + 16, rp[2], rp[3]);
            lds_v2u64(rbase + 32, rp[4], rp[5]);
            lds_v2u64(rbase + 48, rp[6], rp[7]);

            // x-term (independent of h, starts early).
            const float accQ = fmaf(xs[s], wihK, biasK);

            // Packed dot product: two chains of depth 4.
            unsigned long long a0 = mul2(wp[0], rp[0]);
            unsigned long long a1 = mul2(wp[1], rp[1]);
            a0 = fma2(wp[2], rp[2], a0);
            a1 = fma2(wp[3], rp[3], a1);
            a0 = fma2(wp[4], rp[4], a0);
            a1 = fma2(wp[5], rp[5], a1);
            a0 = fma2(wp[6], rp[6], a0);
            a1 = fma2(wp[7], rp[7], a1);
            const float2 pr = unpackf2(add2(a0, a1));
            const float acc = (pr.x + pr.y) + accQ;

            // r = 1/(1 + 2^acc)
            r = rcp_approx(1.0f + ex2_approx(acc));

            sts_f32(waddr, r);
            __syncwarp();
        }
    }

    // h = 1 - 2r; out[b] = sum_j h[j]*w_fc[j] + b_fc
    const float h = fmaf(-2.0f, r, 1.0f);
    float v = h * w_fc[j];
    #pragma unroll
    for (int off = 8; off; off >>= 1)
        v += __shfl_xor_sync(0xffffffffu, v, off, 16);
    if (j == 0)
        out[b] = v + b_fc[0];
}

extern "C" void kernel_launch(void* const* d_in, const int* in_sizes, int n_in,
                              void* d_out, int out_size) {
    const float* x    = (const float*)d_in[0];
    const float* w_ih = (const float*)d_in[1];
    const float* w_hh = (const float*)d_in[2];
    const float* b_ih = (const float*)d_in[3];
    const float* b_hh = (const float*)d_in[4];
    const float* w_fc = (const float*)d_in[5];
    const float* b_fc = (const float*)d_in[6];
    float* out = (float*)d_out;

    // 2048 single-warp blocks; 2 batch elements per warp.
    rnn_scan_kernel<<<RNN_B / 2, 32>>>(x, w_ih, w_hh, b_ih, b_hh, w_fc, b_fc, out);
}